// round 1
// baseline (speedup 1.0000x reference)
#include <cuda_runtime.h>
#include <cuda_bf16.h>

typedef __nv_bfloat16 bf16;

// ---------------- problem constants ----------------
#define BATCH   64
#define T_VID   40
#define D_VID   2048
#define HDIM    1024
#define WDIM    512
#define VOCAB   32000
#define MAXLEN  28
#define DECSTEPS (MAXLEN-1)          // 27
#define G3      (3*HDIM)             // 3072

// ---------------- GEMM tiling ----------------
#define BM 64
#define BN 128
#define BK 64
#define SKEW 8
#define SSTRIDE (BK+SKEW)            // 72
#define ASZ (BM*SSTRIDE)             // 4608
#define BSZ (BN*SSTRIDE)             // 9216
#define SMEM_BYTES ((2*ASZ + 2*BSZ)*2)   // 55296

// ---------------- device scratch ----------------
__device__ bf16  g_Wih1[(size_t)G3*D_VID];
__device__ bf16  g_Whh1[(size_t)G3*HDIM];
__device__ bf16  g_Wih2[(size_t)G3*(HDIM+WDIM)];
__device__ bf16  g_Whh2[(size_t)G3*HDIM];
__device__ bf16  g_Wout[(size_t)VOCAB*HDIM];
__device__ bf16  g_vid [(size_t)T_VID*BATCH*D_VID];
__device__ bf16  g_words[(size_t)DECSTEPS*BATCH*WDIM];
__device__ float g_GI1 [(size_t)T_VID*BATCH*G3];
__device__ float g_GI2w[(size_t)DECSTEPS*BATCH*G3];
__device__ float g_gh1 [(size_t)BATCH*G3];
__device__ float g_gi2 [(size_t)BATCH*G3];
__device__ float g_gh2 [(size_t)BATCH*G3];
__device__ float g_h1  [(size_t)BATCH*HDIM];
__device__ float g_h2  [(size_t)BATCH*HDIM];
__device__ bf16  g_h1b [(size_t)BATCH*HDIM];
__device__ bf16  g_h2b [(size_t)BATCH*HDIM];
__device__ bf16  g_H2all[(size_t)DECSTEPS*BATCH*HDIM];

// ---------------- helpers ----------------
__device__ __forceinline__ void cp16(void* s, const void* g) {
    unsigned sa = (unsigned)__cvta_generic_to_shared(s);
    asm volatile("cp.async.cg.shared.global [%0], [%1], 16;\n" :: "r"(sa), "l"(g));
}
__device__ __forceinline__ void cp_commit() {
    asm volatile("cp.async.commit_group;\n" ::: "memory");
}
__device__ __forceinline__ void cp_wait0() {
    asm volatile("cp.async.wait_group 0;\n" ::: "memory");
}
__device__ __forceinline__ void mma16816(float* c, const unsigned* a, const unsigned* b) {
    asm volatile(
        "mma.sync.aligned.m16n8k16.row.col.f32.bf16.bf16.f32 "
        "{%0,%1,%2,%3}, {%4,%5,%6,%7}, {%8,%9}, {%0,%1,%2,%3};\n"
        : "+f"(c[0]), "+f"(c[1]), "+f"(c[2]), "+f"(c[3])
        : "r"(a[0]), "r"(a[1]), "r"(a[2]), "r"(a[3]), "r"(b[0]), "r"(b[1]));
}

// ---------------- bf16 TN GEMM: C[M,N] = A[M,K] * B[N,K]^T (+bias +addend) ----------------
// grid = (N/BN, M/BM), 256 threads. No edge handling (all dims divisible).
// permute_out: row m = t*64+b is written to output row b*27+t (for logits -> d_out).
__global__ void __launch_bounds__(256)
gemm_bf16_tn(const bf16* __restrict__ A, int lda,
             const bf16* __restrict__ B, int ldb,
             float* __restrict__ C, int ldc,
             const float* __restrict__ bias,
             const float* __restrict__ addend, int ld_add,
             int K, int permute_out)
{
    extern __shared__ bf16 smem[];
    bf16* sA = smem;               // [2][BM][SSTRIDE]
    bf16* sB = smem + 2*ASZ;       // [2][BN][SSTRIDE]

    const int tid  = threadIdx.x;
    const int lane = tid & 31;
    const int warp = tid >> 5;
    const int wm   = warp & 1;     // 2 warps over M
    const int wn   = warp >> 1;    // 4 warps over N
    const int bm   = blockIdx.y * BM;
    const int bn   = blockIdx.x * BN;

    float acc[2][4][4];
#pragma unroll
    for (int mi = 0; mi < 2; mi++)
#pragma unroll
        for (int ni = 0; ni < 4; ni++)
#pragma unroll
            for (int q = 0; q < 4; q++) acc[mi][ni][q] = 0.f;

    const int KT = K >> 6;

    auto issue_stage = [&](int st, int kt) {
        const int k0 = kt << 6;
#pragma unroll
        for (int i = 0; i < 2; i++) {
            int ch = tid + (i << 8);
            int r = ch >> 3, c = (ch & 7) << 3;
            cp16(&sA[st*ASZ + r*SSTRIDE + c], A + (size_t)(bm + r)*lda + k0 + c);
        }
#pragma unroll
        for (int i = 0; i < 4; i++) {
            int ch = tid + (i << 8);
            int r = ch >> 3, c = (ch & 7) << 3;
            cp16(&sB[st*BSZ + r*SSTRIDE + c], B + (size_t)(bn + r)*ldb + k0 + c);
        }
        cp_commit();
    };

    issue_stage(0, 0);

    for (int kt = 0; kt < KT; kt++) {
        cp_wait0();
        __syncthreads();
        if (kt + 1 < KT) issue_stage((kt + 1) & 1, kt + 1);

        const bf16* a = sA + (kt & 1) * ASZ;
        const bf16* b = sB + (kt & 1) * BSZ;

#pragma unroll
        for (int kk = 0; kk < 4; kk++) {
            const int kc = kk * 16 + ((lane & 3) << 1);
            unsigned af[2][4];
#pragma unroll
            for (int mi = 0; mi < 2; mi++) {
                int r = wm * 32 + mi * 16 + (lane >> 2);
                af[mi][0] = *(const unsigned*)(a + (size_t)r * SSTRIDE + kc);
                af[mi][1] = *(const unsigned*)(a + (size_t)(r + 8) * SSTRIDE + kc);
                af[mi][2] = *(const unsigned*)(a + (size_t)r * SSTRIDE + kc + 8);
                af[mi][3] = *(const unsigned*)(a + (size_t)(r + 8) * SSTRIDE + kc + 8);
            }
            unsigned bfr[4][2];
#pragma unroll
            for (int ni = 0; ni < 4; ni++) {
                int r = wn * 32 + ni * 8 + (lane >> 2);
                bfr[ni][0] = *(const unsigned*)(b + (size_t)r * SSTRIDE + kc);
                bfr[ni][1] = *(const unsigned*)(b + (size_t)r * SSTRIDE + kc + 8);
            }
#pragma unroll
            for (int mi = 0; mi < 2; mi++)
#pragma unroll
                for (int ni = 0; ni < 4; ni++)
                    mma16816(acc[mi][ni], af[mi], bfr[ni]);
        }
        __syncthreads();
    }

    // epilogue
#pragma unroll
    for (int mi = 0; mi < 2; mi++) {
#pragma unroll
        for (int ni = 0; ni < 4; ni++) {
            int r0 = bm + wm * 32 + mi * 16 + (lane >> 2);
            int c0 = bn + wn * 32 + ni * 8 + ((lane & 3) << 1);
#pragma unroll
            for (int p = 0; p < 2; p++) {
                int row = r0 + p * 8;
                float x0 = acc[mi][ni][p * 2 + 0];
                float x1 = acc[mi][ni][p * 2 + 1];
                if (bias)   { x0 += bias[c0]; x1 += bias[c0 + 1]; }
                if (addend) {
                    const float* ad = addend + (size_t)row * ld_add + c0;
                    x0 += ad[0]; x1 += ad[1];
                }
                size_t orow = permute_out ? (size_t)((row & 63) * DECSTEPS + (row >> 6))
                                          : (size_t)row;
                *(float2*)(C + orow * (size_t)ldc + c0) = make_float2(x0, x1);
            }
        }
    }
}

// ---------------- elementwise kernels ----------------
__global__ void f32_to_bf16_kernel(const float* __restrict__ in, bf16* __restrict__ out, long n2) {
    long i = blockIdx.x * (long)blockDim.x + threadIdx.x;
    long stride = (long)gridDim.x * blockDim.x;
    const float2* in2 = (const float2*)in;
    __nv_bfloat162* o2 = (__nv_bfloat162*)out;
    for (; i < n2; i += stride) o2[i] = __float22bfloat162_rn(in2[i]);
}

// out[(t*64+b)*D + d] = in[(b*40+t)*D + d]
__global__ void vid_permute_kernel(const float* __restrict__ in, bf16* __restrict__ out) {
    const long n2 = (long)T_VID * BATCH * (D_VID / 2);
    long i = blockIdx.x * 256L + threadIdx.x;
    long stride = (long)gridDim.x * 256;
    for (; i < n2; i += stride) {
        long d2 = i & (D_VID/2 - 1);
        long tb = i >> 10;                // D_VID/2 = 1024
        long b = tb & 63, t = tb >> 6;
        float2 v = ((const float2*)in)[((b * T_VID + t) << 10) + d2];
        ((__nv_bfloat162*)out)[i] = __float22bfloat162_rn(v);
    }
}

// out[(t*64+b)*512 + j] = emb[tgt[b*28+t]*512 + j], t<27
__global__ void words_gather_kernel(const int* __restrict__ tgt, const float* __restrict__ emb,
                                    bf16* __restrict__ out) {
    const long n2 = (long)DECSTEPS * BATCH * (WDIM / 2);
    long i = blockIdx.x * 256L + threadIdx.x;
    long stride = (long)gridDim.x * 256;
    for (; i < n2; i += stride) {
        long j2 = i & (WDIM/2 - 1);
        long tb = i >> 8;                 // WDIM/2 = 256
        long b = tb & 63, t = tb >> 6;
        int tok = tgt[b * MAXLEN + t];
        float2 v = ((const float2*)emb)[(long)tok * (WDIM/2) + j2];
        ((__nv_bfloat162*)out)[i] = __float22bfloat162_rn(v);
    }
}

__global__ void zero_state_kernel(float* h1, float* h2, bf16* h1b, bf16* h2b) {
    int i = blockIdx.x * 256 + threadIdx.x;   // 65536 total
    h1[i] = 0.f; h2[i] = 0.f;
    h1b[i] = __float2bfloat16(0.f);
    h2b[i] = __float2bfloat16(0.f);
}

__device__ __forceinline__ float sigmf(float x) { return 1.f / (1.f + expf(-x)); }

// GRU gate fusion. gi_stride==0 -> gi is a bias vector broadcast over batch.
__global__ void gru_gate_kernel(const float* __restrict__ gi, int gi_stride,
                                const float* __restrict__ gh,
                                const float* __restrict__ hprev,
                                float* __restrict__ h, bf16* __restrict__ hb,
                                bf16* __restrict__ hb2)
{
    int i = blockIdx.x * 256 + threadIdx.x;   // 65536 = 64*1024
    int b = i >> 10, j = i & 1023;
    const float* g = gi + (size_t)b * gi_stride;
    const float* q = gh + (size_t)b * G3;
    float r = sigmf(g[j]          + q[j]);
    float z = sigmf(g[j + HDIM]   + q[j + HDIM]);
    float n = tanhf(g[j + 2*HDIM] + r * q[j + 2*HDIM]);
    float hv = (1.f - z) * n + z * hprev[i];
    h[i] = hv;
    bf16 hvb = __float2bfloat16(hv);
    hb[i] = hvb;
    if (hb2) hb2[i] = hvb;
}

// in-place log_softmax over rows of 32000 fp32 (one CTA per row)
__global__ void logsoftmax_kernel(float* __restrict__ data) {
    const int n4 = VOCAB / 4;                 // 8000
    float* row = data + (size_t)blockIdx.x * VOCAB;
    float4* r4 = (float4*)row;
    const int tid = threadIdx.x;
    const int lane = tid & 31, warp = tid >> 5;
    __shared__ float sred[8];

    float m = -3.4e38f;
    for (int i = tid; i < n4; i += 256) {
        float4 v = r4[i];
        m = fmaxf(m, fmaxf(fmaxf(v.x, v.y), fmaxf(v.z, v.w)));
    }
#pragma unroll
    for (int o = 16; o; o >>= 1) m = fmaxf(m, __shfl_xor_sync(~0u, m, o));
    if (lane == 0) sred[warp] = m;
    __syncthreads();
    m = sred[0];
#pragma unroll
    for (int k = 1; k < 8; k++) m = fmaxf(m, sred[k]);
    __syncthreads();

    float s = 0.f;
    for (int i = tid; i < n4; i += 256) {
        float4 v = r4[i];
        s += expf(v.x - m) + expf(v.y - m) + expf(v.z - m) + expf(v.w - m);
    }
#pragma unroll
    for (int o = 16; o; o >>= 1) s += __shfl_xor_sync(~0u, s, o);
    if (lane == 0) sred[warp] = s;
    __syncthreads();
    s = sred[0];
#pragma unroll
    for (int k = 1; k < 8; k++) s += sred[k];

    float lse = m + logf(s);
    for (int i = tid; i < n4; i += 256) {
        float4 v = r4[i];
        v.x -= lse; v.y -= lse; v.z -= lse; v.w -= lse;
        r4[i] = v;
    }
}

// ---------------- launcher ----------------
extern "C" void kernel_launch(void* const* d_in, const int* in_sizes, int n_in,
                              void* d_out, int out_size)
{
    const float* vid  = (const float*)d_in[0];
    const int*   tgt  = (const int*)  d_in[1];
    const float* emb  = (const float*)d_in[2];
    const float* Wih1 = (const float*)d_in[3];
    const float* Whh1 = (const float*)d_in[4];
    const float* bih1 = (const float*)d_in[5];
    const float* bhh1 = (const float*)d_in[6];
    const float* Wih2 = (const float*)d_in[7];
    const float* Whh2 = (const float*)d_in[8];
    const float* bih2 = (const float*)d_in[9];
    const float* bhh2 = (const float*)d_in[10];
    const float* Wout = (const float*)d_in[11];
    const float* bout = (const float*)d_in[12];
    float* out = (float*)d_out;

    cudaFuncSetAttribute(gemm_bf16_tn, cudaFuncAttributeMaxDynamicSharedMemorySize, SMEM_BYTES);

    bf16 *pWih1, *pWhh1, *pWih2, *pWhh2, *pWout, *pVid, *pWords, *ph1b, *ph2b, *pH2all;
    float *pGI1, *pGI2w, *pgh1, *pgi2, *pgh2, *ph1, *ph2;
    cudaGetSymbolAddress((void**)&pWih1, g_Wih1);
    cudaGetSymbolAddress((void**)&pWhh1, g_Whh1);
    cudaGetSymbolAddress((void**)&pWih2, g_Wih2);
    cudaGetSymbolAddress((void**)&pWhh2, g_Whh2);
    cudaGetSymbolAddress((void**)&pWout, g_Wout);
    cudaGetSymbolAddress((void**)&pVid,  g_vid);
    cudaGetSymbolAddress((void**)&pWords,g_words);
    cudaGetSymbolAddress((void**)&pGI1,  g_GI1);
    cudaGetSymbolAddress((void**)&pGI2w, g_GI2w);
    cudaGetSymbolAddress((void**)&pgh1,  g_gh1);
    cudaGetSymbolAddress((void**)&pgi2,  g_gi2);
    cudaGetSymbolAddress((void**)&pgh2,  g_gh2);
    cudaGetSymbolAddress((void**)&ph1,   g_h1);
    cudaGetSymbolAddress((void**)&ph2,   g_h2);
    cudaGetSymbolAddress((void**)&ph1b,  g_h1b);
    cudaGetSymbolAddress((void**)&ph2b,  g_h2b);
    cudaGetSymbolAddress((void**)&pH2all,g_H2all);

    // ---- weight / input conversions (fp32 -> bf16) ----
    f32_to_bf16_kernel<<<1024, 256>>>(Wih1, pWih1, (long)G3 * D_VID / 2);
    f32_to_bf16_kernel<<<1024, 256>>>(Whh1, pWhh1, (long)G3 * HDIM / 2);
    f32_to_bf16_kernel<<<1024, 256>>>(Wih2, pWih2, (long)G3 * (HDIM+WDIM) / 2);
    f32_to_bf16_kernel<<<1024, 256>>>(Whh2, pWhh2, (long)G3 * HDIM / 2);
    f32_to_bf16_kernel<<<2048, 256>>>(Wout, pWout, (long)VOCAB * HDIM / 2);
    vid_permute_kernel<<<2048, 256>>>(vid, pVid);
    words_gather_kernel<<<512, 256>>>(tgt, emb, pWords);
    zero_state_kernel<<<256, 256>>>(ph1, ph2, ph1b, ph2b);

    // ---- batched pre-GEMMs ----
    // GI1[t*64+b] = x_t(b) @ W_ih1^T + b_ih1     (2560 x 3072 x 2048)
    gemm_bf16_tn<<<dim3(G3/BN, (T_VID*BATCH)/BM), 256, SMEM_BYTES>>>(
        pVid, D_VID, pWih1, D_VID, pGI1, G3, bih1, nullptr, 0, D_VID, 0);
    // GI2w[t*64+b] = w_t(b) @ W_ih2[:,H:]^T      (1728 x 3072 x 512)
    gemm_bf16_tn<<<dim3(G3/BN, (DECSTEPS*BATCH)/BM), 256, SMEM_BYTES>>>(
        pWords, WDIM, pWih2 + HDIM, HDIM+WDIM, pGI2w, G3, nullptr, nullptr, 0, WDIM, 0);

    // ---- encoder: 40 sequential steps ----
    for (int t = 0; t < T_VID; t++) {
        gemm_bf16_tn<<<dim3(G3/BN, 1), 256, SMEM_BYTES>>>(
            ph1b, HDIM, pWhh1, HDIM, pgh1, G3, bhh1, nullptr, 0, HDIM, 0);
        gru_gate_kernel<<<256, 256>>>(pGI1 + (size_t)t*BATCH*G3, G3, pgh1, ph1, ph1, ph1b, nullptr);
        gemm_bf16_tn<<<dim3(G3/BN, 1), 256, SMEM_BYTES>>>(
            ph1b, HDIM, pWih2, HDIM+WDIM, pgi2, G3, bih2, nullptr, 0, HDIM, 0);
        gemm_bf16_tn<<<dim3(G3/BN, 1), 256, SMEM_BYTES>>>(
            ph2b, HDIM, pWhh2, HDIM, pgh2, G3, bhh2, nullptr, 0, HDIM, 0);
        gru_gate_kernel<<<256, 256>>>(pgi2, G3, pgh2, ph2, ph2, ph2b, nullptr);
    }

    // ---- decoder: 27 sequential steps (h2 states collected, logits deferred) ----
    for (int t = 0; t < DECSTEPS; t++) {
        gemm_bf16_tn<<<dim3(G3/BN, 1), 256, SMEM_BYTES>>>(
            ph1b, HDIM, pWhh1, HDIM, pgh1, G3, bhh1, nullptr, 0, HDIM, 0);
        gru_gate_kernel<<<256, 256>>>(bih1, 0, pgh1, ph1, ph1, ph1b, nullptr);   // x = 0
        gemm_bf16_tn<<<dim3(G3/BN, 1), 256, SMEM_BYTES>>>(
            ph1b, HDIM, pWih2, HDIM+WDIM, pgi2, G3, bih2,
            pGI2w + (size_t)t*BATCH*G3, G3, HDIM, 0);
        gemm_bf16_tn<<<dim3(G3/BN, 1), 256, SMEM_BYTES>>>(
            ph2b, HDIM, pWhh2, HDIM, pgh2, G3, bhh2, nullptr, 0, HDIM, 0);
        gru_gate_kernel<<<256, 256>>>(pgi2, G3, pgh2, ph2, ph2, ph2b,
                                      pH2all + (size_t)t*BATCH*HDIM);
    }

    // ---- one big logits GEMM, writing permuted straight into d_out ----
    // (1728 x 32000 x 1024), row t*64+b -> out row b*27+t
    gemm_bf16_tn<<<dim3(VOCAB/BN, (DECSTEPS*BATCH)/BM), 256, SMEM_BYTES>>>(
        pH2all, HDIM, pWout, HDIM, out, VOCAB, bout, nullptr, 0, HDIM, 1);

    // ---- in-place log_softmax over all 1728 rows of d_out ----
    logsoftmax_kernel<<<DECSTEPS*BATCH, 256>>>(out);
}

// round 2
// speedup vs baseline: 1.0885x; 1.0885x over previous
#include <cuda_runtime.h>
#include <cuda_bf16.h>

typedef __nv_bfloat16 bf16;

// ---------------- problem constants ----------------
#define BATCH   64
#define T_VID   40
#define D_VID   2048
#define HDIM    1024
#define WDIM    512
#define VOCAB   32000
#define MAXLEN  28
#define DECSTEPS (MAXLEN-1)          // 27
#define NSTEPS  (T_VID + DECSTEPS)   // 67
#define G3      (3*HDIM)             // 3072

// ---------------- GEMM tiling ----------------
#define BM 64
#define BN 128
#define BK 64
#define SKEW 8
#define SSTRIDE (BK+SKEW)            // 72
#define ASZ (BM*SSTRIDE)             // 4608
#define BSZ (BN*SSTRIDE)             // 9216
#define SMEM_BYTES ((2*ASZ + 2*BSZ)*2)   // 55296

#define NBLK 48                      // persistent kernel CTAs

// ---------------- device scratch ----------------
__device__ bf16  g_Wih1[(size_t)G3*D_VID];
__device__ bf16  g_Whh1[(size_t)G3*HDIM];
__device__ bf16  g_Wih2[(size_t)G3*(HDIM+WDIM)];
__device__ bf16  g_Whh2[(size_t)G3*HDIM];
__device__ bf16  g_Wout[(size_t)VOCAB*HDIM];
__device__ bf16  g_vid [(size_t)T_VID*BATCH*D_VID];
__device__ bf16  g_words[(size_t)DECSTEPS*BATCH*WDIM];
__device__ float g_GI1 [(size_t)T_VID*BATCH*G3];
__device__ float g_GI2w[(size_t)DECSTEPS*BATCH*G3];
__device__ float g_gh1 [(size_t)BATCH*G3];
__device__ float g_gi2 [(size_t)BATCH*G3];
__device__ float g_gh2 [(size_t)BATCH*G3];
__device__ float g_h1  [(size_t)BATCH*HDIM];
__device__ float g_h2  [(size_t)BATCH*HDIM];
__device__ bf16  g_h1b [(size_t)BATCH*HDIM];
__device__ bf16  g_h2b [(size_t)BATCH*HDIM];
__device__ bf16  g_H2all[(size_t)DECSTEPS*BATCH*HDIM];

// barrier state (sense-reversing, survives graph replays)
__device__ unsigned g_bar_count = 0;
__device__ volatile unsigned g_bar_sense = 0;

// ---------------- helpers ----------------
__device__ __forceinline__ void cp16(void* s, const void* g) {
    unsigned sa = (unsigned)__cvta_generic_to_shared(s);
    asm volatile("cp.async.cg.shared.global [%0], [%1], 16;\n" :: "r"(sa), "l"(g));
}
__device__ __forceinline__ void cp_commit() {
    asm volatile("cp.async.commit_group;\n" ::: "memory");
}
__device__ __forceinline__ void cp_wait0() {
    asm volatile("cp.async.wait_group 0;\n" ::: "memory");
}
__device__ __forceinline__ void mma16816(float* c, const unsigned* a, const unsigned* b) {
    asm volatile(
        "mma.sync.aligned.m16n8k16.row.col.f32.bf16.bf16.f32 "
        "{%0,%1,%2,%3}, {%4,%5,%6,%7}, {%8,%9}, {%0,%1,%2,%3};\n"
        : "+f"(c[0]), "+f"(c[1]), "+f"(c[2]), "+f"(c[3])
        : "r"(a[0]), "r"(a[1]), "r"(a[2]), "r"(a[3]), "r"(b[0]), "r"(b[1]));
}
__device__ __forceinline__ float sigmf(float x) { return 1.f / (1.f + expf(-x)); }

// ---------------- device GEMM tile: C[0:64, bn:bn+128] = A[64,K] * B[N,K]^T ----------------
// writes fp32 via __stcg (+bias +addend). 256 threads.
__device__ __forceinline__ void tile_gemm_64x128(
    const bf16* __restrict__ A, int lda,
    const bf16* __restrict__ B, int ldb, int bn,
    float* __restrict__ C, int ldc,
    const float* __restrict__ bias,
    const float* __restrict__ addend, int ld_add,
    int K, bf16* smem)
{
    bf16* sA = smem;
    bf16* sB = smem + 2*ASZ;

    const int tid  = threadIdx.x;
    const int lane = tid & 31;
    const int warp = tid >> 5;
    const int wm   = warp & 1;
    const int wn   = warp >> 1;

    float acc[2][4][4];
#pragma unroll
    for (int mi = 0; mi < 2; mi++)
#pragma unroll
        for (int ni = 0; ni < 4; ni++)
#pragma unroll
            for (int q = 0; q < 4; q++) acc[mi][ni][q] = 0.f;

    const int KT = K >> 6;

    auto issue_stage = [&](int st, int kt) {
        const int k0 = kt << 6;
#pragma unroll
        for (int i = 0; i < 2; i++) {
            int ch = tid + (i << 8);
            int r = ch >> 3, c = (ch & 7) << 3;
            cp16(&sA[st*ASZ + r*SSTRIDE + c], A + (size_t)r*lda + k0 + c);
        }
#pragma unroll
        for (int i = 0; i < 4; i++) {
            int ch = tid + (i << 8);
            int r = ch >> 3, c = (ch & 7) << 3;
            cp16(&sB[st*BSZ + r*SSTRIDE + c], B + (size_t)(bn + r)*ldb + k0 + c);
        }
        cp_commit();
    };

    issue_stage(0, 0);

    for (int kt = 0; kt < KT; kt++) {
        cp_wait0();
        __syncthreads();
        if (kt + 1 < KT) issue_stage((kt + 1) & 1, kt + 1);

        const bf16* a = sA + (kt & 1) * ASZ;
        const bf16* b = sB + (kt & 1) * BSZ;

#pragma unroll
        for (int kk = 0; kk < 4; kk++) {
            const int kc = kk * 16 + ((lane & 3) << 1);
            unsigned af[2][4];
#pragma unroll
            for (int mi = 0; mi < 2; mi++) {
                int r = wm * 32 + mi * 16 + (lane >> 2);
                af[mi][0] = *(const unsigned*)(a + (size_t)r * SSTRIDE + kc);
                af[mi][1] = *(const unsigned*)(a + (size_t)(r + 8) * SSTRIDE + kc);
                af[mi][2] = *(const unsigned*)(a + (size_t)r * SSTRIDE + kc + 8);
                af[mi][3] = *(const unsigned*)(a + (size_t)(r + 8) * SSTRIDE + kc + 8);
            }
            unsigned bfr[4][2];
#pragma unroll
            for (int ni = 0; ni < 4; ni++) {
                int r = wn * 32 + ni * 8 + (lane >> 2);
                bfr[ni][0] = *(const unsigned*)(b + (size_t)r * SSTRIDE + kc);
                bfr[ni][1] = *(const unsigned*)(b + (size_t)r * SSTRIDE + kc + 8);
            }
#pragma unroll
            for (int mi = 0; mi < 2; mi++)
#pragma unroll
                for (int ni = 0; ni < 4; ni++)
                    mma16816(acc[mi][ni], af[mi], bfr[ni]);
        }
        __syncthreads();
    }

#pragma unroll
    for (int mi = 0; mi < 2; mi++) {
#pragma unroll
        for (int ni = 0; ni < 4; ni++) {
            int r0 = wm * 32 + mi * 16 + (lane >> 2);
            int c0 = bn + wn * 32 + ni * 8 + ((lane & 3) << 1);
#pragma unroll
            for (int p = 0; p < 2; p++) {
                int row = r0 + p * 8;
                float x0 = acc[mi][ni][p * 2 + 0];
                float x1 = acc[mi][ni][p * 2 + 1];
                if (bias)   { x0 += __ldg(bias + c0); x1 += __ldg(bias + c0 + 1); }
                if (addend) {
                    const float* ad = addend + (size_t)row * ld_add + c0;
                    x0 += __ldcg(ad); x1 += __ldcg(ad + 1);
                }
                __stcg((float2*)(C + (size_t)row * ldc + c0), make_float2(x0, x1));
            }
        }
    }
}

// ---------------- persistent recurrence megakernel ----------------
__global__ void __launch_bounds__(256)
recurrence_kernel(const bf16* __restrict__ Whh1,
                  const bf16* __restrict__ Wih2,
                  const bf16* __restrict__ Whh2,
                  const float* __restrict__ bih1,
                  const float* __restrict__ bhh1,
                  const float* __restrict__ bih2,
                  const float* __restrict__ bhh2,
                  const float* __restrict__ GI1,
                  const float* __restrict__ GI2w,
                  float* gh1, float* gi2, float* gh2,
                  float* h1, float* h2, bf16* h1b, bf16* h2b, bf16* H2all)
{
    extern __shared__ bf16 smem[];
    const int cid = blockIdx.x;
    const int tid = threadIdx.x;

    __shared__ unsigned s_sense;
    if (tid == 0) s_sense = g_bar_sense;
    __syncthreads();

    auto gsync = [&]() {
        __syncthreads();
        if (tid == 0) {
            unsigned ls = s_sense ^ 1u;
            s_sense = ls;
            __threadfence();
            if (atomicAdd(&g_bar_count, 1u) == NBLK - 1) {
                atomicExch(&g_bar_count, 0u);
                __threadfence();
                g_bar_sense = ls;
            } else {
                while (g_bar_sense != ls) __nanosleep(64);
            }
        }
        __syncthreads();
    };

    for (int t = 0; t < NSTEPS; t++) {
        const bool enc = (t < T_VID);

        // ---- Phase A: gh1 (CTAs 0..23) and gh2 (CTAs 24..47) ----
        if (cid < 24)
            tile_gemm_64x128(h1b, HDIM, Whh1, HDIM, cid * BN,
                             gh1, G3, bhh1, nullptr, 0, HDIM, smem);
        else
            tile_gemm_64x128(h2b, HDIM, Whh2, HDIM, (cid - 24) * BN,
                             gh2, G3, bhh2, nullptr, 0, HDIM, smem);
        gsync();

        // ---- gate1: h1 update ----
        {
            const float* gi = enc ? (GI1 + (size_t)t * BATCH * G3) : bih1;
            const int gstride = enc ? G3 : 0;
            for (int i = cid * 256 + tid; i < BATCH * HDIM; i += NBLK * 256) {
                int b = i >> 10, j = i & 1023;
                const float* g = gi + (size_t)b * gstride;
                const float* q = gh1 + (size_t)b * G3;
                float r = sigmf(__ldcg(g + j)            + __ldcg(q + j));
                float z = sigmf(__ldcg(g + j + HDIM)     + __ldcg(q + j + HDIM));
                float n = tanhf(__ldcg(g + j + 2*HDIM) + r * __ldcg(q + j + 2*HDIM));
                float hv = (1.f - z) * n + z * __ldcg(h1 + i);
                __stcg(h1 + i, hv);
                unsigned short us = __bfloat16_as_ushort(__float2bfloat16(hv));
                __stcg((unsigned short*)h1b + i, us);
            }
        }
        gsync();

        // ---- Phase C: gi2 = h1b @ Wih2[:, :H]^T (+bih2 +word addend) ----
        if (cid < 24)
            tile_gemm_64x128(h1b, HDIM, Wih2, HDIM + WDIM, cid * BN,
                             gi2, G3, bih2,
                             enc ? nullptr : (GI2w + (size_t)(t - T_VID) * BATCH * G3),
                             G3, HDIM, smem);
        gsync();

        // ---- gate2: h2 update (+ collect decoder h2 states) ----
        {
            bf16* h2save = enc ? nullptr : (H2all + (size_t)(t - T_VID) * BATCH * HDIM);
            for (int i = cid * 256 + tid; i < BATCH * HDIM; i += NBLK * 256) {
                int b = i >> 10, j = i & 1023;
                const float* g = gi2 + (size_t)b * G3;
                const float* q = gh2 + (size_t)b * G3;
                float r = sigmf(__ldcg(g + j)            + __ldcg(q + j));
                float z = sigmf(__ldcg(g + j + HDIM)     + __ldcg(q + j + HDIM));
                float n = tanhf(__ldcg(g + j + 2*HDIM) + r * __ldcg(q + j + 2*HDIM));
                float hv = (1.f - z) * n + z * __ldcg(h2 + i);
                __stcg(h2 + i, hv);
                unsigned short us = __bfloat16_as_ushort(__float2bfloat16(hv));
                __stcg((unsigned short*)h2b + i, us);
                if (h2save) __stcg((unsigned short*)h2save + i, us);
            }
        }
        gsync();
    }
}

// ---------------- standalone bf16 TN GEMM (big batched GEMMs) ----------------
__global__ void __launch_bounds__(256)
gemm_bf16_tn(const bf16* __restrict__ A, int lda,
             const bf16* __restrict__ B, int ldb,
             float* __restrict__ C, int ldc,
             const float* __restrict__ bias,
             int K, int permute_out)
{
    extern __shared__ bf16 smem[];
    bf16* sA = smem;
    bf16* sB = smem + 2*ASZ;

    const int tid  = threadIdx.x;
    const int lane = tid & 31;
    const int warp = tid >> 5;
    const int wm   = warp & 1;
    const int wn   = warp >> 1;
    const int bm   = blockIdx.y * BM;
    const int bn   = blockIdx.x * BN;

    float acc[2][4][4];
#pragma unroll
    for (int mi = 0; mi < 2; mi++)
#pragma unroll
        for (int ni = 0; ni < 4; ni++)
#pragma unroll
            for (int q = 0; q < 4; q++) acc[mi][ni][q] = 0.f;

    const int KT = K >> 6;

    auto issue_stage = [&](int st, int kt) {
        const int k0 = kt << 6;
#pragma unroll
        for (int i = 0; i < 2; i++) {
            int ch = tid + (i << 8);
            int r = ch >> 3, c = (ch & 7) << 3;
            cp16(&sA[st*ASZ + r*SSTRIDE + c], A + (size_t)(bm + r)*lda + k0 + c);
        }
#pragma unroll
        for (int i = 0; i < 4; i++) {
            int ch = tid + (i << 8);
            int r = ch >> 3, c = (ch & 7) << 3;
            cp16(&sB[st*BSZ + r*SSTRIDE + c], B + (size_t)(bn + r)*ldb + k0 + c);
        }
        cp_commit();
    };

    issue_stage(0, 0);

    for (int kt = 0; kt < KT; kt++) {
        cp_wait0();
        __syncthreads();
        if (kt + 1 < KT) issue_stage((kt + 1) & 1, kt + 1);

        const bf16* a = sA + (kt & 1) * ASZ;
        const bf16* b = sB + (kt & 1) * BSZ;

#pragma unroll
        for (int kk = 0; kk < 4; kk++) {
            const int kc = kk * 16 + ((lane & 3) << 1);
            unsigned af[2][4];
#pragma unroll
            for (int mi = 0; mi < 2; mi++) {
                int r = wm * 32 + mi * 16 + (lane >> 2);
                af[mi][0] = *(const unsigned*)(a + (size_t)r * SSTRIDE + kc);
                af[mi][1] = *(const unsigned*)(a + (size_t)(r + 8) * SSTRIDE + kc);
                af[mi][2] = *(const unsigned*)(a + (size_t)r * SSTRIDE + kc + 8);
                af[mi][3] = *(const unsigned*)(a + (size_t)(r + 8) * SSTRIDE + kc + 8);
            }
            unsigned bfr[4][2];
#pragma unroll
            for (int ni = 0; ni < 4; ni++) {
                int r = wn * 32 + ni * 8 + (lane >> 2);
                bfr[ni][0] = *(const unsigned*)(b + (size_t)r * SSTRIDE + kc);
                bfr[ni][1] = *(const unsigned*)(b + (size_t)r * SSTRIDE + kc + 8);
            }
#pragma unroll
            for (int mi = 0; mi < 2; mi++)
#pragma unroll
                for (int ni = 0; ni < 4; ni++)
                    mma16816(acc[mi][ni], af[mi], bfr[ni]);
        }
        __syncthreads();
    }

#pragma unroll
    for (int mi = 0; mi < 2; mi++) {
#pragma unroll
        for (int ni = 0; ni < 4; ni++) {
            int r0 = bm + wm * 32 + mi * 16 + (lane >> 2);
            int c0 = bn + wn * 32 + ni * 8 + ((lane & 3) << 1);
#pragma unroll
            for (int p = 0; p < 2; p++) {
                int row = r0 + p * 8;
                float x0 = acc[mi][ni][p * 2 + 0];
                float x1 = acc[mi][ni][p * 2 + 1];
                if (bias)   { x0 += bias[c0]; x1 += bias[c0 + 1]; }
                size_t orow = permute_out ? (size_t)((row & 63) * DECSTEPS + (row >> 6))
                                          : (size_t)row;
                *(float2*)(C + orow * (size_t)ldc + c0) = make_float2(x0, x1);
            }
        }
    }
}

// ---------------- elementwise kernels ----------------
__global__ void f32_to_bf16_kernel(const float* __restrict__ in, bf16* __restrict__ out, long n2) {
    long i = blockIdx.x * (long)blockDim.x + threadIdx.x;
    long stride = (long)gridDim.x * blockDim.x;
    const float2* in2 = (const float2*)in;
    __nv_bfloat162* o2 = (__nv_bfloat162*)out;
    for (; i < n2; i += stride) o2[i] = __float22bfloat162_rn(in2[i]);
}

__global__ void vid_permute_kernel(const float* __restrict__ in, bf16* __restrict__ out) {
    const long n2 = (long)T_VID * BATCH * (D_VID / 2);
    long i = blockIdx.x * 256L + threadIdx.x;
    long stride = (long)gridDim.x * 256;
    for (; i < n2; i += stride) {
        long d2 = i & (D_VID/2 - 1);
        long tb = i >> 10;
        long b = tb & 63, t = tb >> 6;
        float2 v = ((const float2*)in)[((b * T_VID + t) << 10) + d2];
        ((__nv_bfloat162*)out)[i] = __float22bfloat162_rn(v);
    }
}

__global__ void words_gather_kernel(const int* __restrict__ tgt, const float* __restrict__ emb,
                                    bf16* __restrict__ out) {
    const long n2 = (long)DECSTEPS * BATCH * (WDIM / 2);
    long i = blockIdx.x * 256L + threadIdx.x;
    long stride = (long)gridDim.x * 256;
    for (; i < n2; i += stride) {
        long j2 = i & (WDIM/2 - 1);
        long tb = i >> 8;
        long b = tb & 63, t = tb >> 6;
        int tok = tgt[b * MAXLEN + t];
        float2 v = ((const float2*)emb)[(long)tok * (WDIM/2) + j2];
        ((__nv_bfloat162*)out)[i] = __float22bfloat162_rn(v);
    }
}

__global__ void zero_state_kernel(float* h1, float* h2, bf16* h1b, bf16* h2b) {
    int i = blockIdx.x * 256 + threadIdx.x;
    h1[i] = 0.f; h2[i] = 0.f;
    h1b[i] = __float2bfloat16(0.f);
    h2b[i] = __float2bfloat16(0.f);
}

// in-place log_softmax over rows of 32000 fp32 (one CTA per row)
__global__ void logsoftmax_kernel(float* __restrict__ data) {
    const int n4 = VOCAB / 4;
    float* row = data + (size_t)blockIdx.x * VOCAB;
    float4* r4 = (float4*)row;
    const int tid = threadIdx.x;
    const int lane = tid & 31, warp = tid >> 5;
    __shared__ float sred[8];

    float m = -3.4e38f;
    for (int i = tid; i < n4; i += 256) {
        float4 v = r4[i];
        m = fmaxf(m, fmaxf(fmaxf(v.x, v.y), fmaxf(v.z, v.w)));
    }
#pragma unroll
    for (int o = 16; o; o >>= 1) m = fmaxf(m, __shfl_xor_sync(~0u, m, o));
    if (lane == 0) sred[warp] = m;
    __syncthreads();
    m = sred[0];
#pragma unroll
    for (int k = 1; k < 8; k++) m = fmaxf(m, sred[k]);
    __syncthreads();

    float s = 0.f;
    for (int i = tid; i < n4; i += 256) {
        float4 v = r4[i];
        s += expf(v.x - m) + expf(v.y - m) + expf(v.z - m) + expf(v.w - m);
    }
#pragma unroll
    for (int o = 16; o; o >>= 1) s += __shfl_xor_sync(~0u, s, o);
    if (lane == 0) sred[warp] = s;
    __syncthreads();
    s = sred[0];
#pragma unroll
    for (int k = 1; k < 8; k++) s += sred[k];

    float lse = m + logf(s);
    for (int i = tid; i < n4; i += 256) {
        float4 v = r4[i];
        v.x -= lse; v.y -= lse; v.z -= lse; v.w -= lse;
        r4[i] = v;
    }
}

// ---------------- launcher ----------------
extern "C" void kernel_launch(void* const* d_in, const int* in_sizes, int n_in,
                              void* d_out, int out_size)
{
    const float* vid  = (const float*)d_in[0];
    const int*   tgt  = (const int*)  d_in[1];
    const float* emb  = (const float*)d_in[2];
    const float* Wih1 = (const float*)d_in[3];
    const float* Whh1 = (const float*)d_in[4];
    const float* bih1 = (const float*)d_in[5];
    const float* bhh1 = (const float*)d_in[6];
    const float* Wih2 = (const float*)d_in[7];
    const float* Whh2 = (const float*)d_in[8];
    const float* bih2 = (const float*)d_in[9];
    const float* bhh2 = (const float*)d_in[10];
    const float* Wout = (const float*)d_in[11];
    const float* bout = (const float*)d_in[12];
    float* out = (float*)d_out;

    cudaFuncSetAttribute(gemm_bf16_tn, cudaFuncAttributeMaxDynamicSharedMemorySize, SMEM_BYTES);
    cudaFuncSetAttribute(recurrence_kernel, cudaFuncAttributeMaxDynamicSharedMemorySize, SMEM_BYTES);

    bf16 *pWih1, *pWhh1, *pWih2, *pWhh2, *pWout, *pVid, *pWords, *ph1b, *ph2b, *pH2all;
    float *pGI1, *pGI2w, *pgh1, *pgi2, *pgh2, *ph1, *ph2;
    cudaGetSymbolAddress((void**)&pWih1, g_Wih1);
    cudaGetSymbolAddress((void**)&pWhh1, g_Whh1);
    cudaGetSymbolAddress((void**)&pWih2, g_Wih2);
    cudaGetSymbolAddress((void**)&pWhh2, g_Whh2);
    cudaGetSymbolAddress((void**)&pWout, g_Wout);
    cudaGetSymbolAddress((void**)&pVid,  g_vid);
    cudaGetSymbolAddress((void**)&pWords,g_words);
    cudaGetSymbolAddress((void**)&pGI1,  g_GI1);
    cudaGetSymbolAddress((void**)&pGI2w, g_GI2w);
    cudaGetSymbolAddress((void**)&pgh1,  g_gh1);
    cudaGetSymbolAddress((void**)&pgi2,  g_gi2);
    cudaGetSymbolAddress((void**)&pgh2,  g_gh2);
    cudaGetSymbolAddress((void**)&ph1,   g_h1);
    cudaGetSymbolAddress((void**)&ph2,   g_h2);
    cudaGetSymbolAddress((void**)&ph1b,  g_h1b);
    cudaGetSymbolAddress((void**)&ph2b,  g_h2b);
    cudaGetSymbolAddress((void**)&pH2all,g_H2all);

    // ---- conversions (fp32 -> bf16) ----
    f32_to_bf16_kernel<<<1024, 256>>>(Wih1, pWih1, (long)G3 * D_VID / 2);
    f32_to_bf16_kernel<<<1024, 256>>>(Whh1, pWhh1, (long)G3 * HDIM / 2);
    f32_to_bf16_kernel<<<1024, 256>>>(Wih2, pWih2, (long)G3 * (HDIM+WDIM) / 2);
    f32_to_bf16_kernel<<<1024, 256>>>(Whh2, pWhh2, (long)G3 * HDIM / 2);
    f32_to_bf16_kernel<<<2048, 256>>>(Wout, pWout, (long)VOCAB * HDIM / 2);
    vid_permute_kernel<<<2048, 256>>>(vid, pVid);
    words_gather_kernel<<<512, 256>>>(tgt, emb, pWords);
    zero_state_kernel<<<256, 256>>>(ph1, ph2, ph1b, ph2b);

    // ---- batched pre-GEMMs ----
    gemm_bf16_tn<<<dim3(G3/BN, (T_VID*BATCH)/BM), 256, SMEM_BYTES>>>(
        pVid, D_VID, pWih1, D_VID, pGI1, G3, bih1, D_VID, 0);
    gemm_bf16_tn<<<dim3(G3/BN, (DECSTEPS*BATCH)/BM), 256, SMEM_BYTES>>>(
        pWords, WDIM, pWih2 + HDIM, HDIM+WDIM, pGI2w, G3, nullptr, WDIM, 0);

    // ---- persistent recurrence: all 67 steps in one kernel ----
    recurrence_kernel<<<NBLK, 256, SMEM_BYTES>>>(
        pWhh1, pWih2, pWhh2,
        bih1, bhh1, bih2, bhh2,
        pGI1, pGI2w,
        pgh1, pgi2, pgh2,
        ph1, ph2, ph1b, ph2b, pH2all);

    // ---- one big logits GEMM, writing permuted straight into d_out ----
    gemm_bf16_tn<<<dim3(VOCAB/BN, (DECSTEPS*BATCH)/BM), 256, SMEM_BYTES>>>(
        pH2all, HDIM, pWout, HDIM, out, VOCAB, bout, HDIM, 1);

    // ---- in-place log_softmax ----
    logsoftmax_kernel<<<DECSTEPS*BATCH, 256>>>(out);
}

// round 3
// speedup vs baseline: 1.3902x; 1.2772x over previous
#include <cuda_runtime.h>
#include <cuda_bf16.h>

typedef __nv_bfloat16 bf16;

// ---------------- problem constants ----------------
#define BATCH   64
#define T_VID   40
#define D_VID   2048
#define HDIM    1024
#define WDIM    512
#define VOCAB   32000
#define MAXLEN  28
#define DECSTEPS (MAXLEN-1)          // 27
#define NSTEPS  (T_VID + DECSTEPS)   // 67
#define G3      (3*HDIM)             // 3072

// ---------------- GEMM tiling ----------------
#define SKEW 8
#define SSTRIDE (64+SKEW)            // 72
#define ASZ (64*SSTRIDE)             // 4608

#define NBLK 96                      // persistent kernel CTAs

// ---------------- device scratch ----------------
__device__ bf16  g_Wih1[(size_t)G3*D_VID];
__device__ bf16  g_Whh1[(size_t)G3*HDIM];
__device__ bf16  g_Wih2[(size_t)G3*(HDIM+WDIM)];
__device__ bf16  g_Whh2[(size_t)G3*HDIM];
__device__ bf16  g_Wout[(size_t)VOCAB*HDIM];
__device__ bf16  g_vid [(size_t)T_VID*BATCH*D_VID];
__device__ bf16  g_words[(size_t)DECSTEPS*BATCH*WDIM];
__device__ float g_GI1 [(size_t)T_VID*BATCH*G3];
__device__ float g_GI2w[(size_t)DECSTEPS*BATCH*G3];
__device__ float g_gh1 [(size_t)BATCH*G3];
__device__ float g_gi2 [(size_t)BATCH*G3];
__device__ float g_gh2 [(size_t)BATCH*G3];
__device__ float g_h1  [(size_t)BATCH*HDIM];
__device__ float g_h2  [(size_t)BATCH*HDIM];
__device__ bf16  g_h1b [(size_t)BATCH*HDIM];
__device__ bf16  g_h2b [(size_t)BATCH*HDIM];
__device__ bf16  g_H2all[(size_t)DECSTEPS*BATCH*HDIM];

// barrier state (sense-reversing, survives graph replays)
__device__ unsigned g_bar_count = 0;
__device__ volatile unsigned g_bar_sense = 0;

// ---------------- helpers ----------------
__device__ __forceinline__ void cp16(void* s, const void* g) {
    unsigned sa = (unsigned)__cvta_generic_to_shared(s);
    asm volatile("cp.async.cg.shared.global [%0], [%1], 16;\n" :: "r"(sa), "l"(g));
}
__device__ __forceinline__ void cp_commit() {
    asm volatile("cp.async.commit_group;\n" ::: "memory");
}
__device__ __forceinline__ void cp_wait0() {
    asm volatile("cp.async.wait_group 0;\n" ::: "memory");
}
__device__ __forceinline__ void mma16816(float* c, const unsigned* a, const unsigned* b) {
    asm volatile(
        "mma.sync.aligned.m16n8k16.row.col.f32.bf16.bf16.f32 "
        "{%0,%1,%2,%3}, {%4,%5,%6,%7}, {%8,%9}, {%0,%1,%2,%3};\n"
        : "+f"(c[0]), "+f"(c[1]), "+f"(c[2]), "+f"(c[3])
        : "r"(a[0]), "r"(a[1]), "r"(a[2]), "r"(a[3]), "r"(b[0]), "r"(b[1]));
}
__device__ __forceinline__ float sigmf(float x) { return 1.f / (1.f + expf(-x)); }

// ---------------- templated GEMM tile ----------------
// C[bm:bm+64, bn:bn+TBN] = A[*,K] * B[N,K]^T (+bias +addend). 256 threads.
// Warp layout: 2 (M) x 4 (N); warp tile = 32 x (TBN/4). NI = TBN/32 n-frags.
template<int TBN>
__device__ __forceinline__ void tile_gemm(
    const bf16* __restrict__ A, int lda,
    const bf16* __restrict__ B, int ldb, int bn,
    float* __restrict__ C, int ldc, int bm,
    const float* __restrict__ bias,
    const float* __restrict__ addend, int ld_add,
    int K, bf16* smem, int permute_out)
{
    constexpr int NI   = TBN / 32;
    constexpr int BSZT = TBN * SSTRIDE;

    bf16* sA = smem;
    bf16* sB = smem + 2*ASZ;

    const int tid  = threadIdx.x;
    const int lane = tid & 31;
    const int warp = tid >> 5;
    const int wm   = warp & 1;
    const int wn   = warp >> 1;

    float acc[2][NI][4];
#pragma unroll
    for (int mi = 0; mi < 2; mi++)
#pragma unroll
        for (int ni = 0; ni < NI; ni++)
#pragma unroll
            for (int q = 0; q < 4; q++) acc[mi][ni][q] = 0.f;

    const int KT = K >> 6;

    auto issue_stage = [&](int st, int kt) {
        const int k0 = kt << 6;
#pragma unroll
        for (int i = 0; i < 2; i++) {
            int ch = tid + (i << 8);
            int r = ch >> 3, c = (ch & 7) << 3;
            cp16(&sA[st*ASZ + r*SSTRIDE + c], A + (size_t)(bm + r)*lda + k0 + c);
        }
#pragma unroll
        for (int i = 0; i < NI; i++) {
            int ch = tid + (i << 8);
            int r = ch >> 3, c = (ch & 7) << 3;
            cp16(&sB[st*BSZT + r*SSTRIDE + c], B + (size_t)(bn + r)*ldb + k0 + c);
        }
        cp_commit();
    };

    issue_stage(0, 0);

    for (int kt = 0; kt < KT; kt++) {
        cp_wait0();
        __syncthreads();
        if (kt + 1 < KT) issue_stage((kt + 1) & 1, kt + 1);

        const bf16* a = sA + (kt & 1) * ASZ;
        const bf16* b = sB + (kt & 1) * BSZT;

#pragma unroll
        for (int kk = 0; kk < 4; kk++) {
            const int kc = kk * 16 + ((lane & 3) << 1);
            unsigned af[2][4];
#pragma unroll
            for (int mi = 0; mi < 2; mi++) {
                int r = wm * 32 + mi * 16 + (lane >> 2);
                af[mi][0] = *(const unsigned*)(a + (size_t)r * SSTRIDE + kc);
                af[mi][1] = *(const unsigned*)(a + (size_t)(r + 8) * SSTRIDE + kc);
                af[mi][2] = *(const unsigned*)(a + (size_t)r * SSTRIDE + kc + 8);
                af[mi][3] = *(const unsigned*)(a + (size_t)(r + 8) * SSTRIDE + kc + 8);
            }
            unsigned bfr[NI][2];
#pragma unroll
            for (int ni = 0; ni < NI; ni++) {
                int r = wn * (TBN/4) + ni * 8 + (lane >> 2);
                bfr[ni][0] = *(const unsigned*)(b + (size_t)r * SSTRIDE + kc);
                bfr[ni][1] = *(const unsigned*)(b + (size_t)r * SSTRIDE + kc + 8);
            }
#pragma unroll
            for (int mi = 0; mi < 2; mi++)
#pragma unroll
                for (int ni = 0; ni < NI; ni++)
                    mma16816(acc[mi][ni], af[mi], bfr[ni]);
        }
        __syncthreads();
    }

#pragma unroll
    for (int mi = 0; mi < 2; mi++) {
#pragma unroll
        for (int ni = 0; ni < NI; ni++) {
            int r0 = wm * 32 + mi * 16 + (lane >> 2);
            int c0 = bn + wn * (TBN/4) + ni * 8 + ((lane & 3) << 1);
#pragma unroll
            for (int p = 0; p < 2; p++) {
                int row = bm + r0 + p * 8;
                float x0 = acc[mi][ni][p * 2 + 0];
                float x1 = acc[mi][ni][p * 2 + 1];
                if (bias)   { x0 += __ldg(bias + c0); x1 += __ldg(bias + c0 + 1); }
                if (addend) {
                    const float* ad = addend + (size_t)row * ld_add + c0;
                    x0 += __ldcg(ad); x1 += __ldcg(ad + 1);
                }
                size_t orow = permute_out ? (size_t)((row & 63) * DECSTEPS + (row >> 6))
                                          : (size_t)row;
                __stcg((float2*)(C + orow * (size_t)ldc + c0), make_float2(x0, x1));
            }
        }
    }
}

// ---------------- standalone GEMM kernel ----------------
template<int TBN>
__global__ void __launch_bounds__(256)
gemm_kernel(const bf16* __restrict__ A, int lda,
            const bf16* __restrict__ B, int ldb,
            float* __restrict__ C, int ldc,
            const float* __restrict__ bias,
            int K, int permute_out)
{
    extern __shared__ bf16 smem[];
    tile_gemm<TBN>(A, lda, B, ldb, blockIdx.x * TBN, C, ldc, blockIdx.y * 64,
                   bias, nullptr, 0, K, smem, permute_out);
}

// ---------------- persistent recurrence megakernel ----------------
__global__ void __launch_bounds__(256)
recurrence_kernel(const bf16* __restrict__ Whh1,
                  const bf16* __restrict__ Wih2,
                  const bf16* __restrict__ Whh2,
                  const float* __restrict__ bih1,
                  const float* __restrict__ bhh1,
                  const float* __restrict__ bih2,
                  const float* __restrict__ bhh2,
                  const float* __restrict__ GI1,
                  const float* __restrict__ GI2w,
                  float* gh1, float* gi2, float* gh2,
                  float* h1, float* h2, bf16* h1b, bf16* h2b, bf16* H2all)
{
    extern __shared__ bf16 smem[];
    const int cid = blockIdx.x;
    const int tid = threadIdx.x;

    __shared__ unsigned s_sense;
    if (tid == 0) s_sense = g_bar_sense;
    __syncthreads();

    auto gsync = [&]() {
        __syncthreads();
        if (tid == 0) {
            unsigned ls = s_sense ^ 1u;
            s_sense = ls;
            __threadfence();
            if (atomicAdd(&g_bar_count, 1u) == NBLK - 1) {
                atomicExch(&g_bar_count, 0u);
                __threadfence();
                g_bar_sense = ls;
            } else {
                while (g_bar_sense != ls) __nanosleep(32);
            }
        }
        __syncthreads();
    };

    // ---- zero initial state (every replay) ----
    for (int i = cid * 256 + tid; i < BATCH * HDIM; i += NBLK * 256) {
        __stcg(h1 + i, 0.f);
        __stcg(h2 + i, 0.f);
        __stcg((unsigned short*)h1b + i, (unsigned short)0);
        __stcg((unsigned short*)h2b + i, (unsigned short)0);
    }
    gsync();

    for (int t = 0; t < NSTEPS; t++) {
        const bool enc = (t < T_VID);

        // ---- Phase A: gh1 (CTAs 0..47, BN=64) + gh2 (CTAs 48..95, BN=64) ----
        if (cid < 48)
            tile_gemm<64>(h1b, HDIM, Whh1, HDIM, cid * 64,
                          gh1, G3, 0, bhh1, nullptr, 0, HDIM, smem, 0);
        else
            tile_gemm<64>(h2b, HDIM, Whh2, HDIM, (cid - 48) * 64,
                          gh2, G3, 0, bhh2, nullptr, 0, HDIM, smem, 0);
        gsync();

        // ---- gate1: h1 update ----
        {
            const float* gi = enc ? (GI1 + (size_t)t * BATCH * G3) : bih1;
            const int gstride = enc ? G3 : 0;
            for (int i = cid * 256 + tid; i < BATCH * HDIM; i += NBLK * 256) {
                int b = i >> 10, j = i & 1023;
                const float* g = gi + (size_t)b * gstride;
                const float* q = gh1 + (size_t)b * G3;
                float r = sigmf(__ldcg(g + j)            + __ldcg(q + j));
                float z = sigmf(__ldcg(g + j + HDIM)     + __ldcg(q + j + HDIM));
                float n = tanhf(__ldcg(g + j + 2*HDIM) + r * __ldcg(q + j + 2*HDIM));
                float hv = (1.f - z) * n + z * __ldcg(h1 + i);
                __stcg(h1 + i, hv);
                unsigned short us = __bfloat16_as_ushort(__float2bfloat16(hv));
                __stcg((unsigned short*)h1b + i, us);
            }
        }
        gsync();

        // ---- Phase C: gi2 = h1b @ Wih2[:, :H]^T (all 96 CTAs, BN=32) ----
        tile_gemm<32>(h1b, HDIM, Wih2, HDIM + WDIM, cid * 32,
                      gi2, G3, 0, bih2,
                      enc ? nullptr : (GI2w + (size_t)(t - T_VID) * BATCH * G3),
                      G3, HDIM, smem, 0);
        gsync();

        // ---- gate2: h2 update (+ collect decoder h2 states) ----
        {
            bf16* h2save = enc ? nullptr : (H2all + (size_t)(t - T_VID) * BATCH * HDIM);
            for (int i = cid * 256 + tid; i < BATCH * HDIM; i += NBLK * 256) {
                int b = i >> 10, j = i & 1023;
                const float* g = gi2 + (size_t)b * G3;
                const float* q = gh2 + (size_t)b * G3;
                float r = sigmf(__ldcg(g + j)            + __ldcg(q + j));
                float z = sigmf(__ldcg(g + j + HDIM)     + __ldcg(q + j + HDIM));
                float n = tanhf(__ldcg(g + j + 2*HDIM) + r * __ldcg(q + j + 2*HDIM));
                float hv = (1.f - z) * n + z * __ldcg(h2 + i);
                __stcg(h2 + i, hv);
                unsigned short us = __bfloat16_as_ushort(__float2bfloat16(hv));
                __stcg((unsigned short*)h2b + i, us);
                if (h2save) __stcg((unsigned short*)h2save + i, us);
            }
        }
        gsync();
    }
}

// ---------------- fused fp32->bf16 conversion of all 5 weights ----------------
#define CN1 ((long)G3*D_VID/2)
#define CN2 ((long)G3*HDIM/2)
#define CN3 ((long)G3*(HDIM+WDIM)/2)
#define CN4 ((long)G3*HDIM/2)
#define CN5 ((long)VOCAB*HDIM/2)
__global__ void conv_all_kernel(const float* __restrict__ a1, bf16* o1,
                                const float* __restrict__ a2, bf16* o2,
                                const float* __restrict__ a3, bf16* o3,
                                const float* __restrict__ a4, bf16* o4,
                                const float* __restrict__ a5, bf16* o5)
{
    const long total = CN1 + CN2 + CN3 + CN4 + CN5;
    long i = blockIdx.x * 256L + threadIdx.x;
    long stride = (long)gridDim.x * 256;
    for (; i < total; i += stride) {
        const float2* src; __nv_bfloat162* dst; long j = i;
        if (j < CN1) { src = (const float2*)a1; dst = (__nv_bfloat162*)o1; }
        else if ((j -= CN1) < CN2) { src = (const float2*)a2; dst = (__nv_bfloat162*)o2; }
        else if ((j -= CN2) < CN3) { src = (const float2*)a3; dst = (__nv_bfloat162*)o3; }
        else if ((j -= CN3) < CN4) { src = (const float2*)a4; dst = (__nv_bfloat162*)o4; }
        else { j -= CN4; src = (const float2*)a5; dst = (__nv_bfloat162*)o5; }
        dst[j] = __float22bfloat162_rn(src[j]);
    }
}

// ---------------- fused vid-permute + word-gather ----------------
#define PN_VID ((long)T_VID*BATCH*(D_VID/2))
#define PN_WRD ((long)DECSTEPS*BATCH*(WDIM/2))
__global__ void permgather_kernel(const float* __restrict__ vid, bf16* __restrict__ vout,
                                  const int* __restrict__ tgt, const float* __restrict__ emb,
                                  bf16* __restrict__ wout)
{
    const long total = PN_VID + PN_WRD;
    long i = blockIdx.x * 256L + threadIdx.x;
    long stride = (long)gridDim.x * 256;
    for (; i < total; i += stride) {
        if (i < PN_VID) {
            long d2 = i & (D_VID/2 - 1);
            long tb = i >> 10;
            long b = tb & 63, t = tb >> 6;
            float2 v = ((const float2*)vid)[((b * T_VID + t) << 10) + d2];
            ((__nv_bfloat162*)vout)[i] = __float22bfloat162_rn(v);
        } else {
            long k = i - PN_VID;
            long j2 = k & (WDIM/2 - 1);
            long tb = k >> 8;
            long b = tb & 63, t = tb >> 6;
            int tok = tgt[b * MAXLEN + t];
            float2 v = ((const float2*)emb)[(long)tok * (WDIM/2) + j2];
            ((__nv_bfloat162*)wout)[k] = __float22bfloat162_rn(v);
        }
    }
}

// ---------------- in-place log_softmax over rows of 32000 fp32 ----------------
__global__ void logsoftmax_kernel(float* __restrict__ data) {
    const int n4 = VOCAB / 4;
    float* row = data + (size_t)blockIdx.x * VOCAB;
    float4* r4 = (float4*)row;
    const int tid = threadIdx.x;
    const int lane = tid & 31, warp = tid >> 5;
    __shared__ float sred[8];

    float m = -3.4e38f;
    for (int i = tid; i < n4; i += 256) {
        float4 v = r4[i];
        m = fmaxf(m, fmaxf(fmaxf(v.x, v.y), fmaxf(v.z, v.w)));
    }
#pragma unroll
    for (int o = 16; o; o >>= 1) m = fmaxf(m, __shfl_xor_sync(~0u, m, o));
    if (lane == 0) sred[warp] = m;
    __syncthreads();
    m = sred[0];
#pragma unroll
    for (int k = 1; k < 8; k++) m = fmaxf(m, sred[k]);
    __syncthreads();

    float s = 0.f;
    for (int i = tid; i < n4; i += 256) {
        float4 v = r4[i];
        s += expf(v.x - m) + expf(v.y - m) + expf(v.z - m) + expf(v.w - m);
    }
#pragma unroll
    for (int o = 16; o; o >>= 1) s += __shfl_xor_sync(~0u, s, o);
    if (lane == 0) sred[warp] = s;
    __syncthreads();
    s = sred[0];
#pragma unroll
    for (int k = 1; k < 8; k++) s += sred[k];

    float lse = m + logf(s);
    for (int i = tid; i < n4; i += 256) {
        float4 v = r4[i];
        v.x -= lse; v.y -= lse; v.z -= lse; v.w -= lse;
        r4[i] = v;
    }
}

// ---------------- launcher ----------------
#define SM_REC   ((2*ASZ + 2*64*SSTRIDE)*2)     // 36864
#define SM_G256  ((2*ASZ + 2*256*SSTRIDE)*2)    // 92160

extern "C" void kernel_launch(void* const* d_in, const int* in_sizes, int n_in,
                              void* d_out, int out_size)
{
    const float* vid  = (const float*)d_in[0];
    const int*   tgt  = (const int*)  d_in[1];
    const float* emb  = (const float*)d_in[2];
    const float* Wih1 = (const float*)d_in[3];
    const float* Whh1 = (const float*)d_in[4];
    const float* bih1 = (const float*)d_in[5];
    const float* bhh1 = (const float*)d_in[6];
    const float* Wih2 = (const float*)d_in[7];
    const float* Whh2 = (const float*)d_in[8];
    const float* bih2 = (const float*)d_in[9];
    const float* bhh2 = (const float*)d_in[10];
    const float* Wout = (const float*)d_in[11];
    const float* bout = (const float*)d_in[12];
    float* out = (float*)d_out;

    cudaFuncSetAttribute(gemm_kernel<256>, cudaFuncAttributeMaxDynamicSharedMemorySize, SM_G256);
    cudaFuncSetAttribute(recurrence_kernel, cudaFuncAttributeMaxDynamicSharedMemorySize, SM_REC);

    bf16 *pWih1, *pWhh1, *pWih2, *pWhh2, *pWout, *pVid, *pWords, *ph1b, *ph2b, *pH2all;
    float *pGI1, *pGI2w, *pgh1, *pgi2, *pgh2, *ph1, *ph2;
    cudaGetSymbolAddress((void**)&pWih1, g_Wih1);
    cudaGetSymbolAddress((void**)&pWhh1, g_Whh1);
    cudaGetSymbolAddress((void**)&pWih2, g_Wih2);
    cudaGetSymbolAddress((void**)&pWhh2, g_Whh2);
    cudaGetSymbolAddress((void**)&pWout, g_Wout);
    cudaGetSymbolAddress((void**)&pVid,  g_vid);
    cudaGetSymbolAddress((void**)&pWords,g_words);
    cudaGetSymbolAddress((void**)&pGI1,  g_GI1);
    cudaGetSymbolAddress((void**)&pGI2w, g_GI2w);
    cudaGetSymbolAddress((void**)&pgh1,  g_gh1);
    cudaGetSymbolAddress((void**)&pgi2,  g_gi2);
    cudaGetSymbolAddress((void**)&pgh2,  g_gh2);
    cudaGetSymbolAddress((void**)&ph1,   g_h1);
    cudaGetSymbolAddress((void**)&ph2,   g_h2);
    cudaGetSymbolAddress((void**)&ph1b,  g_h1b);
    cudaGetSymbolAddress((void**)&ph2b,  g_h2b);
    cudaGetSymbolAddress((void**)&pH2all,g_H2all);

    // launch 0: all weight conversions fused
    conv_all_kernel<<<2048, 256>>>(Wih1, pWih1, Whh1, pWhh1, Wih2, pWih2,
                                   Whh2, pWhh2, Wout, pWout);
    // launch 1: vid permute + word gather fused
    permgather_kernel<<<2048, 256>>>(vid, pVid, tgt, emb, pWords);

    // launch 2: GI1 = vid @ W_ih1^T + b_ih1   (2560 x 3072 x 2048)
    gemm_kernel<256><<<dim3(G3/256, (T_VID*BATCH)/64), 256, SM_G256>>>(
        pVid, D_VID, pWih1, D_VID, pGI1, G3, bih1, D_VID, 0);
    // launch 3: GI2w = words @ W_ih2[:,H:]^T  (1728 x 3072 x 512)
    gemm_kernel<256><<<dim3(G3/256, (DECSTEPS*BATCH)/64), 256, SM_G256>>>(
        pWords, WDIM, pWih2 + HDIM, HDIM+WDIM, pGI2w, G3, nullptr, WDIM, 0);

    // launch 4: persistent recurrence (all 67 steps)
    recurrence_kernel<<<NBLK, 256, SM_REC>>>(
        pWhh1, pWih2, pWhh2,
        bih1, bhh1, bih2, bhh2,
        pGI1, pGI2w,
        pgh1, pgi2, pgh2,
        ph1, ph2, ph1b, ph2b, pH2all);

    // launch 5: logits (1728 x 32000 x 1024), permuted into d_out
    gemm_kernel<256><<<dim3(VOCAB/256, (DECSTEPS*BATCH)/64), 256, SM_G256>>>(
        pH2all, HDIM, pWout, HDIM, out, VOCAB, bout, HDIM, 1);

    // launch 6: in-place log_softmax
    logsoftmax_kernel<<<DECSTEPS*BATCH, 256>>>(out);
}